// round 6
// baseline (speedup 1.0000x reference)
#include <cuda_runtime.h>
#include <cuda_bf16.h>
#include <cstdio>

// Problem constants
#define BB 8
#define NN 1024
#define DD 256
#define HH 8
#define DKV 64
#define HD 512   // H * DK

// Scratch: head-major [B, H, N, 64] for Q, K, V, and attention output.
__device__ float g_Q[(size_t)BB * HH * NN * DKV];
__device__ float g_K[(size_t)BB * HH * NN * DKV];
__device__ float g_V[(size_t)BB * HH * NN * DKV];
__device__ float g_A[(size_t)BB * HH * NN * DKV];

// ---------------------------------------------------------------------------
// Kernel 1: fused QKV projection GEMM.
// X[8192,256] @ W[256,512] -> head-major dst[B,H,N,64].
// Block tile 64x64, BK=16, 256 threads, 4x4 register microtile.
// grid = (128 m-tiles, 8 heads, 3 {Wq,Wk,Wv})
// ---------------------------------------------------------------------------
__global__ __launch_bounds__(256) void qkv_kernel(
    const float* __restrict__ X,
    const float* __restrict__ Wq,
    const float* __restrict__ Wk,
    const float* __restrict__ Wv)
{
    __shared__ float As[16][68];  // A transposed: [k][m]
    __shared__ float Ws[16][68];  // [k][n]

    const int bx = blockIdx.x;      // m tile
    const int head = blockIdx.y;    // 0..7
    const int z = blockIdx.z;       // which projection
    const float* W = (z == 0) ? Wq : (z == 1) ? Wk : Wv;
    float* dst = (z == 0) ? g_Q : (z == 1) ? g_K : g_V;

    const int tid = threadIdx.x;
    const int tx = tid & 15, ty = tid >> 4;
    const int m0 = bx * 64;
    const int n0 = head * 64;

    const int la_m = tid >> 2;          // 0..63
    const int la_k = (tid & 3) * 4;     // 0,4,8,12
    const int lw_k = tid >> 4;          // 0..15
    const int lw_n = (tid & 15) * 4;    // 0..60

    float acc[4][4] = {};

    for (int k0 = 0; k0 < DD; k0 += 16) {
        float4 av = *(const float4*)(X + (size_t)(m0 + la_m) * DD + k0 + la_k);
        As[la_k + 0][la_m] = av.x;
        As[la_k + 1][la_m] = av.y;
        As[la_k + 2][la_m] = av.z;
        As[la_k + 3][la_m] = av.w;
        *(float4*)&Ws[lw_k][lw_n] =
            *(const float4*)(W + (size_t)(k0 + lw_k) * HD + n0 + lw_n);
        __syncthreads();
#pragma unroll
        for (int k = 0; k < 16; k++) {
            float4 a = *(float4*)&As[k][ty * 4];
            float4 w = *(float4*)&Ws[k][tx * 4];
            float ai[4] = {a.x, a.y, a.z, a.w};
            float wj[4] = {w.x, w.y, w.z, w.w};
#pragma unroll
            for (int i = 0; i < 4; i++)
#pragma unroll
                for (int j = 0; j < 4; j++) acc[i][j] += ai[i] * wj[j];
        }
        __syncthreads();
    }

    // Epilogue: head-major scatter. row-tiles never straddle batches (64|1024).
    const int r0 = m0 + ty * 4;
#pragma unroll
    for (int i = 0; i < 4; i++) {
        const int row = r0 + i;
        const int b = row >> 10, n = row & 1023;
        float4 o = make_float4(acc[i][0], acc[i][1], acc[i][2], acc[i][3]);
        *(float4*)(dst + ((((size_t)b * HH + head) * NN + n) * DKV) + tx * 4) = o;
    }
}

// ---------------------------------------------------------------------------
// Kernel 2: flash-attention with edge-mask bias + per-key distance modulation.
// One block per (b,h, 64-row s-tile). 256 threads. Online softmax.
// logit = (q.k/8 + (1-mask)*(-1e9)) * dw[t]
// K tile stored TRANSPOSED in smem (Ks[k][t]) so the S-loop LDS.128 reads are
// conflict-free (lane-varying index is the contiguous column).
// Dynamic smem: Qs,Ks,Vs,Ps each 64x68 floats = 69632 B.
// ---------------------------------------------------------------------------
__global__ __launch_bounds__(256) void attn_kernel(
    const float* __restrict__ em,   // [B,1,N,N]
    const float* __restrict__ dw)   // [B,N]
{
    extern __shared__ float smem[];
    float (*Qs)[68] = (float(*)[68])(smem);                 // [s][dk]
    float (*Ks)[68] = (float(*)[68])(smem + 64 * 68);       // [dk][t]  (transposed!)
    float (*Vs)[68] = (float(*)[68])(smem + 2 * 64 * 68);   // [t][dv]
    float (*Ps)[68] = (float(*)[68])(smem + 3 * 64 * 68);   // [s][t]

    const int bh = blockIdx.y;
    const int b = bh >> 3;
    const int s0 = blockIdx.x * 64;
    const int tid = threadIdx.x;
    const int tx = tid & 15, ty = tid >> 4;
    const int r0 = ty * 4, c0 = tx * 4;

    const float* Qg = g_Q + (size_t)bh * NN * DKV;
    const float* Kg = g_K + (size_t)bh * NN * DKV;
    const float* Vg = g_V + (size_t)bh * NN * DKV;

    const int lm = tid >> 2;            // 0..63 (row for Q/V loads, t-row for K)
    const int lk = (tid & 3) * 16;      // 0,16,32,48
    const int kc = (tid & 3) * 4;       // 0,4,8,12 (K col chunk base)

    // Load Q tile once
#pragma unroll
    for (int u = 0; u < 4; u++)
        *(float4*)&Qs[lm][lk + u * 4] =
            *(const float4*)(Qg + (size_t)(s0 + lm) * DKV + lk + u * 4);

    float m_r[4], l_r[4], o[4][4];
#pragma unroll
    for (int i = 0; i < 4; i++) {
        m_r[i] = -1e30f; l_r[i] = 0.f;
#pragma unroll
        for (int j = 0; j < 4; j++) o[i][j] = 0.f;
    }

    for (int t0 = 0; t0 < NN; t0 += 64) {
        __syncthreads();   // prior O-accum done with Ps/Vs; Q visible on iter 0
#pragma unroll
        for (int u = 0; u < 4; u++) {
            // V: natural layout [t][dv]
            *(float4*)&Vs[lm][lk + u * 4] =
                *(const float4*)(Vg + (size_t)(t0 + lm) * DKV + lk + u * 4);
            // K: transposed store Ks[dk][t]
            float4 kvv = *(const float4*)(Kg + (size_t)(t0 + lm) * DKV + kc + u * 16);
            Ks[kc + u * 16 + 0][lm] = kvv.x;
            Ks[kc + u * 16 + 1][lm] = kvv.y;
            Ks[kc + u * 16 + 2][lm] = kvv.z;
            Ks[kc + u * 16 + 3][lm] = kvv.w;
        }
        __syncthreads();

        // Prefetch mask + distance weights for this tile (cover LDG latency
        // with the S-loop FFMAs below).
        float4 d4 = *(const float4*)(dw + b * NN + t0 + c0);
        float4 mk[4];
#pragma unroll
        for (int i = 0; i < 4; i++)
            mk[i] = *(const float4*)(em + ((size_t)b * NN + (s0 + r0 + i)) * NN + t0 + c0);

        // S = Q K^T, 4x4 microtile; Ks read along contiguous t (conflict-free)
        float s[4][4] = {};
#pragma unroll
        for (int k0 = 0; k0 < 64; k0 += 4) {
            float4 q[4], kv[4];
#pragma unroll
            for (int i = 0; i < 4; i++) q[i] = *(float4*)&Qs[r0 + i][k0];
#pragma unroll
            for (int kk = 0; kk < 4; kk++) kv[kk] = *(float4*)&Ks[k0 + kk][c0];
#pragma unroll
            for (int i = 0; i < 4; i++) {
                s[i][0] += q[i].x * kv[0].x + q[i].y * kv[1].x + q[i].z * kv[2].x + q[i].w * kv[3].x;
                s[i][1] += q[i].x * kv[0].y + q[i].y * kv[1].y + q[i].z * kv[2].y + q[i].w * kv[3].y;
                s[i][2] += q[i].x * kv[0].z + q[i].y * kv[1].z + q[i].z * kv[2].z + q[i].w * kv[3].z;
                s[i][3] += q[i].x * kv[0].w + q[i].y * kv[1].w + q[i].z * kv[2].w + q[i].w * kv[3].w;
            }
        }

        // scale + mask bias + distance modulation
        const float dwv[4] = {d4.x, d4.y, d4.z, d4.w};
#pragma unroll
        for (int i = 0; i < 4; i++) {
            float mv[4] = {mk[i].x, mk[i].y, mk[i].z, mk[i].w};
#pragma unroll
            for (int j = 0; j < 4; j++)
                s[i][j] = (s[i][j] * 0.125f + (1.0f - mv[j]) * (-1.0e9f)) * dwv[j];
        }

        // Online softmax: rows owned by 16 tx-lanes (lane bits 0..3)
#pragma unroll
        for (int i = 0; i < 4; i++) {
            float mx = fmaxf(fmaxf(s[i][0], s[i][1]), fmaxf(s[i][2], s[i][3]));
#pragma unroll
            for (int w = 1; w < 16; w <<= 1)
                mx = fmaxf(mx, __shfl_xor_sync(0xffffffff, mx, w));
            const float m_new = fmaxf(m_r[i], mx);
            const float alpha = __expf(m_r[i] - m_new);
            float psum = 0.f;
#pragma unroll
            for (int j = 0; j < 4; j++) {
                s[i][j] = __expf(s[i][j] - m_new);
                psum += s[i][j];
            }
#pragma unroll
            for (int w = 1; w < 16; w <<= 1)
                psum += __shfl_xor_sync(0xffffffff, psum, w);
            l_r[i] = l_r[i] * alpha + psum;
            m_r[i] = m_new;
#pragma unroll
            for (int j = 0; j < 4; j++) o[i][j] *= alpha;
            *(float4*)&Ps[r0 + i][c0] = make_float4(s[i][0], s[i][1], s[i][2], s[i][3]);
        }
        __syncthreads();

        // O += P @ V   (Vs read along contiguous dv: conflict-free)
#pragma unroll
        for (int t = 0; t < 64; t += 4) {
            float4 p[4], vv[4];
#pragma unroll
            for (int i = 0; i < 4; i++) p[i] = *(float4*)&Ps[r0 + i][t];
#pragma unroll
            for (int u = 0; u < 4; u++) vv[u] = *(float4*)&Vs[t + u][c0];
#pragma unroll
            for (int i = 0; i < 4; i++) {
                o[i][0] += p[i].x * vv[0].x + p[i].y * vv[1].x + p[i].z * vv[2].x + p[i].w * vv[3].x;
                o[i][1] += p[i].x * vv[0].y + p[i].y * vv[1].y + p[i].z * vv[2].y + p[i].w * vv[3].y;
                o[i][2] += p[i].x * vv[0].z + p[i].y * vv[1].z + p[i].z * vv[2].z + p[i].w * vv[3].z;
                o[i][3] += p[i].x * vv[0].w + p[i].y * vv[1].w + p[i].z * vv[2].w + p[i].w * vv[3].w;
            }
        }
    }

    // Normalize and write head-major attention output
    float* Ag = g_A + (size_t)bh * NN * DKV;
#pragma unroll
    for (int i = 0; i < 4; i++) {
        const float inv = 1.0f / l_r[i];
        float4 ov = make_float4(o[i][0] * inv, o[i][1] * inv, o[i][2] * inv, o[i][3] * inv);
        *(float4*)(Ag + (size_t)(s0 + r0 + i) * DKV + c0) = ov;
    }
}

// ---------------------------------------------------------------------------
// Kernel 3: output projection. attn[B,N,H*DV] @ Wo[512,256] + bo.
// Reads g_A head-major with reindexing. grid = (128, 4).
// ---------------------------------------------------------------------------
__global__ __launch_bounds__(256) void out_kernel(
    const float* __restrict__ Wo,
    const float* __restrict__ bo,
    float* __restrict__ out)
{
    __shared__ float As[16][68];
    __shared__ float Ws[16][68];

    const int bx = blockIdx.x;   // m tile
    const int byy = blockIdx.y;  // n tile
    const int tid = threadIdx.x;
    const int tx = tid & 15, ty = tid >> 4;
    const int m0 = bx * 64, n0 = byy * 64;

    const int la_m = tid >> 2;
    const int la_k = (tid & 3) * 4;
    const int lw_k = tid >> 4;
    const int lw_n = (tid & 15) * 4;

    float acc[4][4] = {};

    for (int k0 = 0; k0 < HD; k0 += 16) {
        const int row = m0 + la_m;
        const int b = row >> 10, n = row & 1023;
        const int k = k0 + la_k;
        const int h = k >> 6, dv = k & 63;
        float4 av = *(const float4*)(g_A + ((((size_t)b * HH + h) * NN + n) * DKV) + dv);
        As[la_k + 0][la_m] = av.x;
        As[la_k + 1][la_m] = av.y;
        As[la_k + 2][la_m] = av.z;
        As[la_k + 3][la_m] = av.w;
        *(float4*)&Ws[lw_k][lw_n] =
            *(const float4*)(Wo + (size_t)(k0 + lw_k) * DD + n0 + lw_n);
        __syncthreads();
#pragma unroll
        for (int k2 = 0; k2 < 16; k2++) {
            float4 a = *(float4*)&As[k2][ty * 4];
            float4 w = *(float4*)&Ws[k2][tx * 4];
            float ai[4] = {a.x, a.y, a.z, a.w};
            float wj[4] = {w.x, w.y, w.z, w.w};
#pragma unroll
            for (int i = 0; i < 4; i++)
#pragma unroll
                for (int j = 0; j < 4; j++) acc[i][j] += ai[i] * wj[j];
        }
        __syncthreads();
    }

    float4 bias = *(const float4*)(bo + n0 + tx * 4);
    const int r0g = m0 + ty * 4;
#pragma unroll
    for (int i = 0; i < 4; i++) {
        float4 ov = make_float4(acc[i][0] + bias.x, acc[i][1] + bias.y,
                                acc[i][2] + bias.z, acc[i][3] + bias.w);
        *(float4*)(out + (size_t)(r0g + i) * DD + n0 + tx * 4) = ov;
    }
}

// ---------------------------------------------------------------------------
extern "C" void kernel_launch(void* const* d_in, const int* in_sizes, int n_in,
                              void* d_out, int out_size)
{
    const float* X  = (const float*)d_in[0];
    const float* em = (const float*)d_in[1];
    const float* dw = (const float*)d_in[2];
    const float* Wq = (const float*)d_in[3];
    const float* Wk = (const float*)d_in[4];
    const float* Wv = (const float*)d_in[5];
    const float* Wo = (const float*)d_in[6];
    const float* bo = (const float*)d_in[7];
    float* out = (float*)d_out;

    const int attn_smem = 4 * 64 * 68 * (int)sizeof(float);  // 69632 B
    cudaFuncSetAttribute(attn_kernel,
                         cudaFuncAttributeMaxDynamicSharedMemorySize, attn_smem);

    qkv_kernel<<<dim3(128, 8, 3), 256>>>(X, Wq, Wk, Wv);
    attn_kernel<<<dim3(16, 64), 256, attn_smem>>>(em, dw);
    out_kernel<<<dim3(128, 4), 256>>>(Wo, bo, out);
}